// round 7
// baseline (speedup 1.0000x reference)
#include <cuda_runtime.h>
#include <cstdint>

#define B_   32
#define L_   256
#define T_   1600
#define C_   40
#define PADM 1.0e12f

// ---------------- scratch (__device__ globals; no allocation allowed) ----------------
__device__ __align__(16) float g_coefA[B_ * C_ * 2 * L_];   // invvar, duplicated pairs
__device__ __align__(16) float g_coefB[B_ * C_ * 2 * L_];   // mu*invvar, duplicated pairs
__device__ __align__(16) float g_t3 [B_ * L_];
__device__ __align__(16) float g_mlv[B_ * L_];

// ---------------- packed f32x2 helpers (sm_103a) ----------------
__device__ __forceinline__ unsigned long long pack2(float lo, float hi) {
    unsigned long long r;
    asm("mov.b64 %0, {%1,%2};" : "=l"(r) : "f"(lo), "f"(hi));
    return r;
}
#define FFMA2_ACC(d, a, b) \
    asm("fma.rn.f32x2 %0, %1, %2, %0;" : "+l"(d) : "l"(a), "l"(b))
#define FFMA2(d, a, b, c) \
    asm("fma.rn.f32x2 %0, %1, %2, %3;" : "=l"(d) : "l"(a), "l"(b), "l"(c))
#define ADD2(d, a, b) \
    asm("add.rn.f32x2 %0, %1, %2;" : "=l"(d) : "l"(a), "l"(b))

// volatile 64-bit shared ld/st (single-instruction mailbox access)
__device__ __forceinline__ uint2 ldsv2v(unsigned a) {
    uint2 r;
    asm volatile("ld.volatile.shared.v2.b32 {%0,%1},[%2];"
                 : "=r"(r.x), "=r"(r.y) : "r"(a));
    return r;
}
__device__ __forceinline__ void stsv2v(unsigned a, unsigned tag, float v) {
    asm volatile("st.volatile.shared.v2.b32 [%0],{%1,%2};"
                 :: "r"(a), "r"(tag), "r"(__float_as_uint(v)));
}

// ---------------- K0: per-(b,l) coefficients ----------------
__global__ void k0_coef(const float* __restrict__ mu_logvar) {
    int idx = blockIdx.x * 256 + threadIdx.x;          // 0 .. B*L-1
    int b = idx >> 8;
    int l = idx & (L_ - 1);
    const float* row = mu_logvar + (size_t)idx * (2 * C_);
    float* A  = g_coefA + (size_t)b * C_ * 2 * L_ + 2 * l;
    float* Bc = g_coefB + (size_t)b * C_ * 2 * L_ + 2 * l;
    float t3 = 0.f, slv = 0.f;
    for (int c = 0; c < C_; c++) {
        float mu = row[c];
        float lv = row[C_ + c];
        float iv = expf(-lv);
        float miv = mu * iv;
        A [c * 2 * L_]     = iv;
        A [c * 2 * L_ + 1] = iv;
        Bc[c * 2 * L_]     = miv;
        Bc[c * 2 * L_ + 1] = miv;
        t3 = fmaf(mu, miv, t3);
        slv += lv;
    }
    g_t3 [idx] = t3;
    g_mlv[idx] = slv * (1.0f / C_);
}

// ---------------- K1: lp[b][l][t] via packed FFMA2 GEMM ----------------
__global__ __launch_bounds__(256) void k1_lp(const float* __restrict__ z,
                                             float* __restrict__ lp_out) {
    __shared__ __align__(16) float zs [C_][64];
    __shared__ __align__(16) float z2s[C_][64];
    int b  = blockIdx.z;
    int l0 = blockIdx.y * 128;
    int t0 = blockIdx.x * 64;
    int tid = threadIdx.x;

    const float* zb = z + (size_t)b * C_ * T_ + t0;
    for (int i = tid; i < C_ * 64; i += 256) {
        int c = i >> 6, j = i & 63;
        float v = zb[(size_t)c * T_ + j];
        zs [c][j] = v;
        z2s[c][j] = v * v;
    }
    __syncthreads();

    int lg = tid >> 3, tg = tid & 7;
    int lbase = l0 + lg * 4;

    unsigned long long s1[4][4], s2[4][4];
#pragma unroll
    for (int r = 0; r < 4; r++)
#pragma unroll
        for (int j = 0; j < 4; j++) { s1[r][j] = 0ull; s2[r][j] = 0ull; }

    const float* cA = g_coefA + (size_t)b * C_ * 2 * L_ + 2 * lbase;
    const float* cB = g_coefB + (size_t)b * C_ * 2 * L_ + 2 * lbase;

#pragma unroll 2
    for (int c = 0; c < C_; c++) {
        ulonglong2 aL = *(const ulonglong2*)(cA + (size_t)c * 2 * L_);
        ulonglong2 aH = *(const ulonglong2*)(cA + (size_t)c * 2 * L_ + 4);
        ulonglong2 bL = *(const ulonglong2*)(cB + (size_t)c * 2 * L_);
        ulonglong2 bH = *(const ulonglong2*)(cB + (size_t)c * 2 * L_ + 4);
        unsigned long long ar[4] = {aL.x, aL.y, aH.x, aH.y};
        unsigned long long br[4] = {bL.x, bL.y, bH.x, bH.y};
        ulonglong2 q0 = *(const ulonglong2*)&z2s[c][tg * 8];
        ulonglong2 q1 = *(const ulonglong2*)&z2s[c][tg * 8 + 4];
        ulonglong2 w0 = *(const ulonglong2*)&zs [c][tg * 8];
        ulonglong2 w1 = *(const ulonglong2*)&zs [c][tg * 8 + 4];
        unsigned long long z2p[4] = {q0.x, q0.y, q1.x, q1.y};
        unsigned long long zp [4] = {w0.x, w0.y, w1.x, w1.y};
#pragma unroll
        for (int r = 0; r < 4; r++) {
#pragma unroll
            for (int j = 0; j < 4; j++) {
                FFMA2_ACC(s1[r][j], ar[r], z2p[j]);
                FFMA2_ACC(s2[r][j], br[r], zp[j]);
            }
        }
    }

    float4 t34 = *(const float4*)(g_t3  + b * L_ + lbase);
    float4 mv4 = *(const float4*)(g_mlv + b * L_ + lbase);
    float t3a[4] = {t34.x, t34.y, t34.z, t34.w};
    float mva[4] = {mv4.x, mv4.y, mv4.z, mv4.w};
    unsigned long long m2 = pack2(-2.0f, -2.0f);
    unsigned long long c1 = pack2(-0.0125f, -0.0125f);   // -0.5/C
#pragma unroll
    for (int r = 0; r < 4; r++) {
        unsigned long long tp = pack2(t3a[r], t3a[r]);
        unsigned long long dp = pack2(-0.5f * mva[r], -0.5f * mva[r]);
        unsigned long long o[4];
#pragma unroll
        for (int j = 0; j < 4; j++) {
            unsigned long long mse;
            FFMA2(mse, s2[r][j], m2, s1[r][j]);   // s1 - 2*s2
            ADD2(mse, mse, tp);                   // + t3
            FFMA2(o[j], mse, c1, dp);             // *(-1/80) + (-0.5*mlv)
        }
        float* orow = lp_out + ((size_t)b * L_ + lbase + r) * T_ + t0 + tg * 8;
        ((ulonglong2*)orow)[0] = make_ulonglong2(o[0], o[1]);
        ((ulonglong2*)orow)[1] = make_ulonglong2(o[2], o[3]);
    }
}

// ---------------- K2: split DP. blocks 0..31 = alpha(loss), 32..63 = beta(align) ----
// smem layout (bytes):
//   [0, 51200)          D ballot words [T_][8]         (beta only)
//   [51200, 57600)      path[T_]                       (beta only)
//   [57600, 160000)     mailbox: 8 warps x 1600 slots x 8B {tag=t+1, val}
#define SMB_D    0
#define SMB_PATH 51200
#define SMB_MB   57600
#define SMB_TOT  160000

__global__ __launch_bounds__(256, 1) void k2_split(const float* __restrict__ lp,
                                                   const int* __restrict__ tlen,
                                                   const int* __restrict__ mlen,
                                                   float* __restrict__ out_loss,
                                                   float* __restrict__ out_align) {
    extern __shared__ unsigned char smraw[];
    unsigned smbase = (unsigned)__cvta_generic_to_shared(smraw);
    unsigned mb = smbase + SMB_MB;

    bool is_beta = (blockIdx.x >= B_);
    int b = is_beta ? (blockIdx.x - B_) : blockIdx.x;
    int l = threadIdx.x;
    int w = l >> 5, lane = l & 31;
    int ml = mlen[b], tl = tlen[b];
    int mlm1 = ml - 1, tlm1 = tl - 1;
    const float* p = lp + ((size_t)b * L_ + l) * T_;

    unsigned mb_self = mb + (unsigned)w * 12800u;
    unsigned mb_src  = mb + (unsigned)((w + 7) & 7) * 12800u;

    // zero mailbox tags (whole region, 6400 uint4)
    {
        uint4* m4 = (uint4*)(smraw + SMB_MB);
        uint4 zz = make_uint4(0u, 0u, 0u, 0u);
        for (int i = l; i < 6400; i += 256) m4[i] = zz;
    }

    // beta blocks zero their alignment slab while DP spins up
    if (is_beta) {
        float4* ap = (float4*)(out_align + (size_t)b * T_ * L_);
        float4 z4 = make_float4(0.f, 0.f, 0.f, 0.f);
        for (int i = l; i < (T_ * L_) / 4; i += 256) ap[i] = z4;
    }

    float4 vcur = *(const float4*)p;           // lp[t=0..3]
    float cur = (l == 0) ? vcur.x : -PADM;     // alpha(0) or beta(0)

    if (lane == 31) stsv2v(mb_self, 1u, -PADM);   // t=0 boundary (lane31 never l==0)
    __syncthreads();

    float4 vnext = *(const float4*)(p + 4);
    unsigned* D = (unsigned*)smraw;

    if (!is_beta) {
        // ---------------- alpha: logaddexp forward, loss only ----------------
        float a = cur;
        for (int k = 0; k < T_ / 4; k++) {
            float4 vpref = vcur;
            if (k + 2 < T_ / 4) vpref = *(const float4*)(p + 4 * (k + 2));
            float lt[4] = {vcur.x, vcur.y, vcur.z, vcur.w};
#pragma unroll
            for (int j = 0; j < 4; j++) {
                int t = 4 * k + j;
                if (t == 0) continue;
                float mba = -PADM;
                if (w) {                      // warp-uniform branch
                    unsigned saddr = mb_src + (unsigned)(t - 1) * 8u;
                    uint2 s = ldsv2v(saddr);
                    while (s.x != (unsigned)t) s = ldsv2v(saddr);
                    mba = __uint_as_float(s.y);
                }
                float sa = __shfl_up_sync(0xffffffffu, a, 1);
                float am = (lane == 0) ? mba : sa;
                float d  = a - am;
                float m  = fmaxf(a, am);
                float an = m + __logf(1.0f + __expf(-fabsf(d))) + (lt[j] + 1e-7f);
                if (t == mlm1 && l == tlm1) out_loss[b] = -an / (float)ml;
                if (lane == 31) stsv2v(mb_self + (unsigned)t * 8u, (unsigned)(t + 1), an);
                a = an;
            }
            vcur = vnext; vnext = vpref;
        }
        return;
    }

    // ---------------- beta: Viterbi + ballot bits + backtrack + one-hot ----------------
    {
        float bt = cur;
        for (int k = 0; k < T_ / 4; k++) {
            float4 vpref = vcur;
            if (k + 2 < T_ / 4) vpref = *(const float4*)(p + 4 * (k + 2));
            float lt[4] = {vcur.x, vcur.y, vcur.z, vcur.w};
#pragma unroll
            for (int j = 0; j < 4; j++) {
                int t = 4 * k + j;
                if (t == 0) continue;
                unsigned saddr = mb_src + (unsigned)(t - 1) * 8u;
                uint2 s = ldsv2v(saddr);
                while (s.x != (unsigned)t) s = ldsv2v(saddr);
                float mbb = __uint_as_float(s.y);
                float sb = __shfl_up_sync(0xffffffffu, bt, 1);
                float bm, bw;
                if (lane == 0) { bw = mbb; bm = (w == 0) ? -PADM : mbb; }
                else           { bm = sb;  bw = sb; }
                unsigned bal = __ballot_sync(0xffffffffu, bw > bt);
                if (lane == 0) D[(t - 1) * 8 + w] = bal;
                float bn = fmaxf(bt, bm) + lt[j];
                if (lane == 31) stsv2v(mb_self + (unsigned)t * 8u, (unsigned)(t + 1), bn);
                bt = bn;
            }
            vcur = vnext; vnext = vpref;
        }
        // last column (t = T-1): need warp7/w-1 boundary beta at T-1
        {
            unsigned saddr = mb_src + (unsigned)(T_ - 1) * 8u;
            uint2 s = ldsv2v(saddr);
            while (s.x != (unsigned)T_) s = ldsv2v(saddr);
            float mbb = __uint_as_float(s.y);
            float sb = __shfl_up_sync(0xffffffffu, bt, 1);
            float bw = (lane == 0) ? mbb : sb;
            unsigned bal = __ballot_sync(0xffffffffu, bw > bt);
            if (lane == 0) D[(T_ - 1) * 8 + w] = bal;
        }
        __syncthreads();

        int* path = (int*)(smraw + SMB_PATH);
        if (l == 0) {
            int rows = tlm1;
            path[0] = rows;
            int k = 1;
            for (; k + 7 <= mlm1; k += 8) {
                int colbase = mlm1 - k;              // all >= 0
                int w0 = (rows & 255) >> 5;
                int w1 = (w0 + 7) & 7;
                unsigned Wa[8], Wb[8];
#pragma unroll
                for (int d2 = 0; d2 < 8; d2++) {
                    Wa[d2] = D[(colbase - d2) * 8 + w0];
                    Wb[d2] = D[(colbase - d2) * 8 + w1];
                }
#pragma unroll
                for (int d2 = 0; d2 < 8; d2++) {
                    int br = rows & 255;
                    unsigned word = ((br >> 5) == w0) ? Wa[d2] : Wb[d2];
                    int is_go = (word >> (br & 31)) & 1;
                    int tmp = rows - is_go + 1;
                    rows = (tmp > 0 ? tmp : 0) - 1;
                    path[k + d2] = rows;
                }
            }
            for (; k <= mlm1; k++) {
                int col = mlm1 - k;
                int br = rows & 255;
                unsigned word = D[col * 8 + (br >> 5)];
                int is_go = (word >> (br & 31)) & 1;
                int tmp = rows - is_go + 1;
                rows = (tmp > 0 ? tmp : 0) - 1;
                path[k] = rows;
            }
        }
        __syncthreads();

        size_t abase = (size_t)b * T_ * L_;
        for (int t = l; t < ml; t += 256) {
            int r = path[mlm1 - t];
            if (r >= 0) out_align[abase + (size_t)t * L_ + r] = 1.0f;
        }
    }
}

// ---------------- launch ----------------
extern "C" void kernel_launch(void* const* d_in, const int* in_sizes, int n_in,
                              void* d_out, int out_size) {
    const float* mu_logvar = (const float*)d_in[0];   // [B, L, 2C]
    const float* z         = (const float*)d_in[1];   // [B, C, T]
    const int*   tlen      = (const int*)d_in[2];     // [B]
    const int*   mlen      = (const int*)d_in[3];     // [B]

    float* out       = (float*)d_out;
    float* out_loss  = out;                                   // [B]
    float* out_align = out + B_;                              // [B, T, L]
    float* out_lp    = out_align + (size_t)B_ * T_ * L_;      // [B, L, T]

    cudaFuncSetAttribute(k2_split, cudaFuncAttributeMaxDynamicSharedMemorySize,
                         SMB_TOT);

    k0_coef<<<B_, 256>>>(mu_logvar);
    dim3 g1(T_ / 64, L_ / 128, B_);
    k1_lp<<<g1, 256>>>(z, out_lp);
    k2_split<<<2 * B_, 256, SMB_TOT>>>(out_lp, tlen, mlen, out_loss, out_align);
}